// round 16
// baseline (speedup 1.0000x reference)
#include <cuda_runtime.h>
#include <cuda_fp16.h>
#include <cstdint>
#include <math.h>

// ============================================================================
// get_model_pred — fp16 mma.sync (m16n8k16) + ldmatrix + split-barrier.
// Big GEMMs: CTA 128x256 (8 warps of 64x64, 256 thr, 1 CTA/SM) — halves A
// L2 re-reads and amortizes per-chunk overhead. Head: 128x128 / 4 warps.
// Outputs: types_w(4,E) | multiW(4,E) | type_output(E,4) | edge_embed(E,512)
// ============================================================================

#define D 512
#define E_MAX 89700

__device__ __half g_hh [(size_t)E_MAX * D];  // hidden, fp16
__device__ __half g_ph [(size_t)E_MAX * D];  // pred fp16, later edge fp16
__device__ __half g_W1t[D * D];              // We1^T (N x K) fp16
__device__ __half g_W2t[D * D];
__device__ __half g_Wt1t[128 * D];

// Tile rows: 64 fp16 (128B) + 16B pad = 144B stride; ldmatrix walks hit
// banks (4r)%32 — conflict-free. A tile is always 128 rows (18432 B);
// B tile is N64*64 rows.
#define ROWB 144
#define TILE_A_BYTES (128 * ROWB)            // 18432
#define NCH 8                                // K chunks of 64

__device__ __forceinline__ uint32_t smem_u32(const void* p) {
    uint32_t a;
    asm("{ .reg .u64 t; cvta.to.shared.u64 t, %1; cvt.u32.u64 %0, t; }"
        : "=r"(a) : "l"(p));
    return a;
}
__device__ __forceinline__ float gatef(float p) {
    const float BEL = 0.025f;
    const float HI  = 1.0f / 2.2f + 0.025f;
    return (p <= BEL) ? 0.0f : ((p >= HI) ? 1.0f : 2.2f * (p - BEL));
}
__device__ __forceinline__ void cpa16(uint32_t dst, const void* src, bool valid) {
    int sz = valid ? 16 : 0;
    asm volatile("cp.async.cg.shared.global [%0], [%1], 16, %2;"
                 :: "r"(dst), "l"(src), "r"(sz) : "memory");
}
#define CP_COMMIT() asm volatile("cp.async.commit_group;" ::: "memory")
#define CP_WAIT(n)  asm volatile("cp.async.wait_group %0;" :: "n"(n) : "memory")
#define BAR_SYNC(id, cnt)   asm volatile("bar.sync %0, %1;"   :: "r"(id), "r"(cnt) : "memory")
#define BAR_ARRIVE(id, cnt) asm volatile("bar.arrive %0, %1;" :: "r"(id), "r"(cnt) : "memory")

__device__ __forceinline__ void mma_f16(float& d0, float& d1, float& d2, float& d3,
                                        uint32_t a0, uint32_t a1, uint32_t a2, uint32_t a3,
                                        uint32_t b0, uint32_t b1) {
    asm volatile(
        "mma.sync.aligned.m16n8k16.row.col.f32.f16.f16.f32 "
        "{%0,%1,%2,%3}, {%4,%5,%6,%7}, {%8,%9}, {%0,%1,%2,%3};"
        : "+f"(d0), "+f"(d1), "+f"(d2), "+f"(d3)
        : "r"(a0), "r"(a1), "r"(a2), "r"(a3), "r"(b0), "r"(b1));
}
__device__ __forceinline__ void ldsm4(uint32_t& r0, uint32_t& r1, uint32_t& r2,
                                      uint32_t& r3, uint32_t addr) {
    asm volatile("ldmatrix.sync.aligned.m8n8.x4.shared.b16 {%0,%1,%2,%3}, [%4];"
                 : "=r"(r0), "=r"(r1), "=r"(r2), "=r"(r3) : "r"(addr));
}

// ---------------------------------------------------------------------------
// Prep kernels
// ---------------------------------------------------------------------------
__global__ void prep_pred(const float4* __restrict__ in, __half2* __restrict__ out, int n4) {
    int i = blockIdx.x * blockDim.x + threadIdx.x;
    if (i < n4) {
        float4 v = in[i];
        out[i * 2 + 0] = __floats2half2_rn(v.x, v.y);
        out[i * 2 + 1] = __floats2half2_rn(v.z, v.w);
    }
}
__global__ void prep_weights(const float* __restrict__ W1, const float* __restrict__ W2,
                             const float* __restrict__ Wt1, __half* __restrict__ o1,
                             __half* __restrict__ o2, __half* __restrict__ o3) {
    int i = blockIdx.x * blockDim.x + threadIdx.x;
    if (i < 262144) {
        int n = i >> 9, k = i & 511;
        o1[i] = __float2half_rn(W1[k * 512 + n]);
    } else if (i < 524288) {
        int j = i - 262144;
        int n = j >> 9, k = j & 511;
        o2[j] = __float2half_rn(W2[k * 512 + n]);
    } else if (i < 589824) {
        int j = i - 524288;
        int n = j >> 9, k = j & 511;
        o3[j] = __float2half_rn(Wt1[k * 128 + n]);
    }
}

// ---------------------------------------------------------------------------
// Tile loader: ROWS x 64 fp16, row stride D halfs, kb in halfs.
// ---------------------------------------------------------------------------
template <int ROWS, int NTHR, bool CHK>
__device__ __forceinline__ void load_tile(
    uint32_t s, const __half* __restrict__ G, int rowBase, int kb, int E, int tid)
{
#pragma unroll
    for (int i = 0; i < ROWS * 8 / NTHR; i++) {
        int idx = i * NTHR + tid;
        int row = idx >> 3, seg = idx & 7;
        bool v = !CHK || (rowBase + row) < E;
        const __half* src = G + (size_t)(rowBase + row) * D + kb + seg * 8;
        cpa16(s + (uint32_t)(row * ROWB + seg * 16), v ? src : G, v);
    }
}

// ---------------------------------------------------------------------------
// Fragment loads (k-step = 32 bytes).
// ---------------------------------------------------------------------------
__device__ __forceinline__ void load_frags(
    uint32_t asB, uint32_t bsB, const uint32_t aOff[4], const uint32_t bOff[4],
    int ks, uint32_t a[4][4], uint32_t b[4][4])
{
    const uint32_t kby = (uint32_t)ks * 32;
#pragma unroll
    for (int mt = 0; mt < 4; mt++)
        ldsm4(a[mt][0], a[mt][1], a[mt][2], a[mt][3], asB + aOff[mt] + kby);
#pragma unroll
    for (int j = 0; j < 4; j++)
        ldsm4(b[j][0], b[j][1], b[j][2], b[j][3], bsB + bOff[j] + kby);
}

// ---------------------------------------------------------------------------
// Mainloop template: N64 = B cols / 64 (4 for big gemm, 2 for head),
// NTHR = N64 * 64 threads. 3-stage ring, split barrier, frag dbl-buffer.
// Phases: pre arrive(1); iter kt syncs 1+(kt&1); arrive(1+((kt+1)&1)) posted
// after the last LDSM of chunk kt (dep-fenced); each phase = 2*NTHR slots.
// ---------------------------------------------------------------------------
template <int N64, int NTHR, bool CHKA>
__device__ __forceinline__ void gemm_mainloop(
    char* smem, const __half* __restrict__ Ag, const __half* __restrict__ Bg,
    int rowBase, int colBase, int E, int tid, float acc[4][8][4],
    int wm, int wn, int lane)
{
    const int TILE_B_BYTES = N64 * 64 * ROWB;
    const int STAGE = TILE_A_BYTES + TILE_B_BYTES;
    const int BCNT = 2 * NTHR;
    const uint32_t sb = smem_u32(smem);

    uint32_t aOff[4], bOff[4];
#pragma unroll
    for (int mt = 0; mt < 4; mt++)
        aOff[mt] = (uint32_t)((wm * 64 + mt * 16 + (lane & 15)) * ROWB
                              + (lane >> 4) * 16);
#pragma unroll
    for (int j = 0; j < 4; j++)
        bOff[j] = (uint32_t)((wn * 64 + j * 16 + (lane & 7) + ((lane & 16) ? 8 : 0)) * ROWB
                             + ((lane >> 3) & 1) * 16);

#pragma unroll
    for (int mt = 0; mt < 4; mt++)
#pragma unroll
        for (int nt = 0; nt < 8; nt++)
#pragma unroll
            for (int r = 0; r < 4; r++) acc[mt][nt][r] = 0.0f;

    load_tile<128, NTHR, CHKA>(sb, Ag, rowBase, 0, E, tid);
    load_tile<N64 * 64, NTHR, false>(sb + TILE_A_BYTES, Bg, colBase, 0, E, tid);
    CP_COMMIT();
    load_tile<128, NTHR, CHKA>(sb + STAGE, Ag, rowBase, 64, E, tid);
    load_tile<N64 * 64, NTHR, false>(sb + STAGE + TILE_A_BYTES, Bg, colBase, 64, E, tid);
    CP_COMMIT();

    BAR_ARRIVE(1, BCNT);

    for (int kt = 0; kt < NCH; kt++) {
        CP_WAIT(1);
        BAR_SYNC(1 + (kt & 1), BCNT);

        const uint32_t asB = sb + (uint32_t)(kt % 3) * STAGE;
        const uint32_t bsB = asB + TILE_A_BYTES;

        uint32_t a[2][4][4], b[2][4][4];
        load_frags(asB, bsB, aOff, bOff, 0, a[0], b[0]);

        if (kt + 2 < NCH) {
            uint32_t st = sb + (uint32_t)((kt + 2) % 3) * STAGE;
            load_tile<128, NTHR, CHKA>(st, Ag, rowBase, (kt + 2) * 64, E, tid);
            load_tile<N64 * 64, NTHR, false>(st + TILE_A_BYTES, Bg, colBase,
                                             (kt + 2) * 64, E, tid);
        }
        CP_COMMIT();

#pragma unroll
        for (int ks = 0; ks < 4; ks++) {
            const int cur = ks & 1;
            if (ks < 3)
                load_frags(asB, bsB, aOff, bOff, ks + 1, a[cur ^ 1], b[cur ^ 1]);
            if (ks == 3) {
                asm volatile("" :: "r"(a[cur][0][3]), "r"(a[cur][1][3]),
                                   "r"(a[cur][2][3]), "r"(a[cur][3][3]),
                                   "r"(b[cur][0][3]), "r"(b[cur][1][3]),
                                   "r"(b[cur][2][3]), "r"(b[cur][3][3]));
                if (kt < NCH - 1) BAR_ARRIVE(1 + ((kt + 1) & 1), BCNT);
            }
#pragma unroll
            for (int mt = 0; mt < 4; mt++)
#pragma unroll
                for (int nt = 0; nt < 8; nt++) {
                    const int j = nt >> 1, h = (nt & 1) * 2;
                    mma_f16(acc[mt][nt][0], acc[mt][nt][1], acc[mt][nt][2], acc[mt][nt][3],
                            a[cur][mt][0], a[cur][mt][1], a[cur][mt][2], a[cur][mt][3],
                            b[cur][j][h], b[cur][j][h + 1]);
                }
        }
    }
    CP_WAIT(0);
    __syncthreads();
}

// ---------------------------------------------------------------------------
// Big GEMM: CTA 128x256, 256 thr (8 warps, 2x4 of 64x64), 1 CTA/SM.
// smem = 3*(18432+36864) = 165888 B. Grid (2, rb) col-fastest.
// MODE 1: h = fp16(relu(acc+bias)). MODE 0: edge fp32 exact + fp16 copy.
// ---------------------------------------------------------------------------
template <int MODE>
__global__ __launch_bounds__(256) void gemm_mma(
    const __half* __restrict__ Ag, const __half* __restrict__ Bt,
    const float* __restrict__ bias, void* __restrict__ Cv,
    __half* __restrict__ Cr, int E)
{
    extern __shared__ __align__(16) char smem[];
    __shared__ float sbias[256];

    const int tid = threadIdx.x;
    const int wid = tid >> 5, lane = tid & 31;
    const int wm = wid >> 2, wn = wid & 3;       // 2x4 warp grid
    const int gid = lane >> 2, tig = lane & 3;
    const int rowBase = blockIdx.y * 128;
    const int colBase = blockIdx.x * 256;

    sbias[tid] = bias[colBase + tid];

    float acc[4][8][4];
    gemm_mainloop<4, 256, true>(smem, Ag, Bt, rowBase, colBase, E, tid, acc,
                                wm, wn, lane);

#pragma unroll
    for (int mt = 0; mt < 4; mt++) {
        const int r0 = rowBase + wm * 64 + mt * 16 + gid;
#pragma unroll
        for (int nt = 0; nt < 8; nt++) {
            const int cl = wn * 64 + nt * 8 + tig * 2;
            const int c = colBase + cl;
            float v0 = acc[mt][nt][0] + sbias[cl];
            float v1 = acc[mt][nt][1] + sbias[cl + 1];
            float v2 = acc[mt][nt][2] + sbias[cl];
            float v3 = acc[mt][nt][3] + sbias[cl + 1];
            if (MODE == 1) {
                __half* Ch = (__half*)Cv;
                if (r0 < E)
                    *(__half2*)&Ch[(size_t)r0 * D + c] =
                        __floats2half2_rn(fmaxf(v0, 0.f), fmaxf(v1, 0.f));
                if (r0 + 8 < E)
                    *(__half2*)&Ch[(size_t)(r0 + 8) * D + c] =
                        __floats2half2_rn(fmaxf(v2, 0.f), fmaxf(v3, 0.f));
            } else {
                float* Cf = (float*)Cv;
                if (r0 < E) {
                    *(float2*)&Cf[(size_t)r0 * D + c] = make_float2(v0, v1);
                    *(__half2*)&Cr[(size_t)r0 * D + c] = __floats2half2_rn(v0, v1);
                }
                if (r0 + 8 < E) {
                    *(float2*)&Cf[(size_t)(r0 + 8) * D + c] = make_float2(v2, v3);
                    *(__half2*)&Cr[(size_t)(r0 + 8) * D + c] = __floats2half2_rn(v2, v3);
                }
            }
        }
    }
}

// ---------------------------------------------------------------------------
// Head: CTA 128x128, 128 thr (4 warps, 2x2 of 64x64). T1 = relu(edge_h @ Wt1
// + bt1), then per-row 128->4 GEMV + softmax + stack + gate.
// ---------------------------------------------------------------------------
__global__ __launch_bounds__(128) void head_mma(
    const __half* __restrict__ EEh, const __half* __restrict__ Wt1t,
    const float* __restrict__ bt1, const float* __restrict__ Wt2,
    const float* __restrict__ bt2, float* __restrict__ out, int E)
{
    extern __shared__ __align__(16) char smem[];
    __shared__ float sWt2[512];
    __shared__ float sbt1[128];

    const int tid = threadIdx.x;
    const int wid = tid >> 5, lane = tid & 31;
    const int wm = wid >> 1, wn = wid & 1;
    const int gid = lane >> 2, tig = lane & 3;
    const int rowBase = blockIdx.x * 128;

    sbt1[tid] = bt1[tid];
    sWt2[tid]       = Wt2[tid];
    sWt2[tid + 128] = Wt2[tid + 128];
    sWt2[tid + 256] = Wt2[tid + 256];
    sWt2[tid + 384] = Wt2[tid + 384];

    float acc[4][8][4];
    gemm_mainloop<2, 128, true>(smem, EEh, Wt1t, rowBase, 0, E, tid, acc,
                                wm, wn, lane);

    float* T1 = (float*)smem;
#pragma unroll
    for (int mt = 0; mt < 4; mt++) {
        const int r = wm * 64 + mt * 16 + gid;
#pragma unroll
        for (int nt = 0; nt < 8; nt++) {
            const int c = wn * 64 + nt * 8 + tig * 2;
            T1[r * 129 + c]           = fmaxf(acc[mt][nt][0] + sbt1[c], 0.f);
            T1[r * 129 + c + 1]       = fmaxf(acc[mt][nt][1] + sbt1[c + 1], 0.f);
            T1[(r + 8) * 129 + c]     = fmaxf(acc[mt][nt][2] + sbt1[c], 0.f);
            T1[(r + 8) * 129 + c + 1] = fmaxf(acc[mt][nt][3] + sbt1[c + 1], 0.f);
        }
    }
    __syncthreads();

    {
        const int gr = rowBase + tid;
        if (gr < E) {
            float t0 = __ldg(&bt2[0]), t1 = __ldg(&bt2[1]);
            float t2 = __ldg(&bt2[2]), t3 = __ldg(&bt2[3]);
            const float* rp = T1 + tid * 129;
#pragma unroll 8
            for (int k = 0; k < 128; k++) {
                float x = rp[k];
                t0 = fmaf(x, sWt2[k * 4 + 0], t0);
                t1 = fmaf(x, sWt2[k * 4 + 1], t1);
                t2 = fmaf(x, sWt2[k * 4 + 2], t2);
                t3 = fmaf(x, sWt2[k * 4 + 3], t3);
            }
            float m = fmaxf(fmaxf(t0, t1), fmaxf(t2, t3));
            float e0 = __expf(t0 - m), e1 = __expf(t1 - m);
            float e2 = __expf(t2 - m), e3 = __expf(t3 - m);
            float inv = 1.0f / (e0 + e1 + e2 + e3);
            float p0 = e0 * inv, p1 = e1 * inv, p2 = e2 * inv, p3 = e3 * inv;
            float tw0 = 1.0f - p0;

            const size_t Es = (size_t)E;
            out[0 * Es + gr] = tw0;
            out[1 * Es + gr] = p1;
            out[2 * Es + gr] = p2;
            out[3 * Es + gr] = p3;
            float* mw = out + 4 * Es;
            mw[0 * Es + gr] = gatef(tw0);
            mw[1 * Es + gr] = gatef(p1);
            mw[2 * Es + gr] = gatef(p2);
            mw[3 * Es + gr] = gatef(p3);
            float* to = out + 8 * Es;
            to[(size_t)gr * 4 + 0] = p0;
            to[(size_t)gr * 4 + 1] = p1;
            to[(size_t)gr * 4 + 2] = p2;
            to[(size_t)gr * 4 + 3] = p3;
        }
    }
}

// ---------------------------------------------------------------------------
extern "C" void kernel_launch(void* const* d_in, const int* in_sizes, int n_in,
                              void* d_out, int out_size)
{
    const float* pred = (const float*)d_in[1];
    const float* We1  = (const float*)d_in[2];
    const float* be1  = (const float*)d_in[3];
    const float* We2  = (const float*)d_in[4];
    const float* be2  = (const float*)d_in[5];
    const float* Wt1  = (const float*)d_in[6];
    const float* bt1  = (const float*)d_in[7];
    const float* Wt2  = (const float*)d_in[8];
    const float* bt2  = (const float*)d_in[9];

    const int E = in_sizes[1] / D;
    float* out  = (float*)d_out;
    float* edge = out + (size_t)12 * E;

    __half *pHH, *pPH, *pW1t, *pW2t, *pWt1t;
    cudaGetSymbolAddress((void**)&pHH,   g_hh);
    cudaGetSymbolAddress((void**)&pPH,   g_ph);
    cudaGetSymbolAddress((void**)&pW1t,  g_W1t);
    cudaGetSymbolAddress((void**)&pW2t,  g_W2t);
    cudaGetSymbolAddress((void**)&pWt1t, g_Wt1t);

    const int G_SMEM = 3 * (TILE_A_BYTES + 4 * 64 * ROWB);   // 165888
    const int H_SMEM = 3 * (TILE_A_BYTES + 2 * 64 * ROWB);   // 110592
    cudaFuncSetAttribute(gemm_mma<1>,
                         cudaFuncAttributeMaxDynamicSharedMemorySize, G_SMEM);
    cudaFuncSetAttribute(gemm_mma<0>,
                         cudaFuncAttributeMaxDynamicSharedMemorySize, G_SMEM);
    cudaFuncSetAttribute(head_mma,
                         cudaFuncAttributeMaxDynamicSharedMemorySize, H_SMEM);

    const int n4 = E * D / 4;
    prep_pred<<<(n4 + 255) / 256, 256>>>((const float4*)pred, (__half2*)pPH, n4);
    prep_weights<<<(589824 + 255) / 256, 256>>>(We1, We2, Wt1, pW1t, pW2t, pWt1t);

    const int rb = (E + 127) / 128;
    dim3 grid(2, rb);   // col block fastest -> A rows shared via L2

    gemm_mma<1><<<grid, 256, G_SMEM>>>(pPH, pW1t, be1, (void*)pHH, nullptr, E);
    gemm_mma<0><<<grid, 256, G_SMEM>>>(pHH, pW2t, be2, (void*)edge, pPH, E);
    head_mma<<<rb, 128, H_SMEM>>>(pPH, pWt1t, bt1, Wt2, bt2, out, E);
}

// round 17
// speedup vs baseline: 1.1930x; 1.1930x over previous
#include <cuda_runtime.h>
#include <cuda_fp16.h>
#include <cstdint>
#include <math.h>

// ============================================================================
// get_model_pred — fp16 mma.sync (m16n8k16) + ldmatrix + split-barrier.
// R15 config (CTA 128x128, 4 warps of 64x64, 2 CTA/SM, 3-stage ring) with
// the cp.async burst spread across the ks-loop and preps merged.
// Outputs: types_w(4,E) | multiW(4,E) | type_output(E,4) | edge_embed(E,512)
// ============================================================================

#define D 512
#define E_MAX 89700

__device__ __half g_hh [(size_t)E_MAX * D];  // hidden, fp16
__device__ __half g_ph [(size_t)E_MAX * D];  // pred fp16, later edge fp16
__device__ __half g_W1t[D * D];              // We1^T (N x K) fp16
__device__ __half g_W2t[D * D];
__device__ __half g_Wt1t[128 * D];

// Tiles: 128 rows x 64 fp16 (128B) + 16B pad = 144B row stride.
// ldmatrix 8-row walks hit banks (4r)%32: conflict-free.
#define ROWB 144
#define TILE_BYTES (128 * ROWB)              // 18432
#define STAGE_BYTES (2 * TILE_BYTES)         // 36864
#define SMEM_TOTAL (3 * STAGE_BYTES)         // 110592 -> 2 CTA/SM
#define NTH 128
#define NCH 8                                // D / 64

__device__ __forceinline__ uint32_t smem_u32(const void* p) {
    uint32_t a;
    asm("{ .reg .u64 t; cvta.to.shared.u64 t, %1; cvt.u32.u64 %0, t; }"
        : "=r"(a) : "l"(p));
    return a;
}
__device__ __forceinline__ float gatef(float p) {
    const float BEL = 0.025f;
    const float HI  = 1.0f / 2.2f + 0.025f;
    return (p <= BEL) ? 0.0f : ((p >= HI) ? 1.0f : 2.2f * (p - BEL));
}
__device__ __forceinline__ void cpa16(uint32_t dst, const void* src, bool valid) {
    int sz = valid ? 16 : 0;
    asm volatile("cp.async.cg.shared.global [%0], [%1], 16, %2;"
                 :: "r"(dst), "l"(src), "r"(sz) : "memory");
}
#define CP_COMMIT() asm volatile("cp.async.commit_group;" ::: "memory")
#define CP_WAIT(n)  asm volatile("cp.async.wait_group %0;" :: "n"(n) : "memory")
#define BAR_SYNC(id)   asm volatile("bar.sync %0, 256;"   :: "r"(id) : "memory")
#define BAR_ARRIVE(id) asm volatile("bar.arrive %0, 256;" :: "r"(id) : "memory")

__device__ __forceinline__ void mma_f16(float& d0, float& d1, float& d2, float& d3,
                                        uint32_t a0, uint32_t a1, uint32_t a2, uint32_t a3,
                                        uint32_t b0, uint32_t b1) {
    asm volatile(
        "mma.sync.aligned.m16n8k16.row.col.f32.f16.f16.f32 "
        "{%0,%1,%2,%3}, {%4,%5,%6,%7}, {%8,%9}, {%0,%1,%2,%3};"
        : "+f"(d0), "+f"(d1), "+f"(d2), "+f"(d3)
        : "r"(a0), "r"(a1), "r"(a2), "r"(a3), "r"(b0), "r"(b1));
}
__device__ __forceinline__ void ldsm4(uint32_t& r0, uint32_t& r1, uint32_t& r2,
                                      uint32_t& r3, uint32_t addr) {
    asm volatile("ldmatrix.sync.aligned.m8n8.x4.shared.b16 {%0,%1,%2,%3}, [%4];"
                 : "=r"(r0), "=r"(r1), "=r"(r2), "=r"(r3) : "r"(addr));
}

// ---------------------------------------------------------------------------
// Prep: pred fp32->fp16 + weights transpose/convert, single launch.
// pred: n4 float4 slots; weights: 589824 elements after that.
// ---------------------------------------------------------------------------
__global__ void prep_all(const float4* __restrict__ pred, __half2* __restrict__ ph,
                         const float* __restrict__ W1, const float* __restrict__ W2,
                         const float* __restrict__ Wt1, __half* __restrict__ o1,
                         __half* __restrict__ o2, __half* __restrict__ o3, int n4) {
    int i = blockIdx.x * blockDim.x + threadIdx.x;
    if (i < n4) {
        float4 v = pred[i];
        ph[i * 2 + 0] = __floats2half2_rn(v.x, v.y);
        ph[i * 2 + 1] = __floats2half2_rn(v.z, v.w);
        return;
    }
    int w = i - n4;
    if (w < 262144) {
        int n = w >> 9, k = w & 511;
        o1[w] = __float2half_rn(W1[k * 512 + n]);
    } else if (w < 524288) {
        int j = w - 262144;
        int n = j >> 9, k = j & 511;
        o2[j] = __float2half_rn(W2[k * 512 + n]);
    } else if (w < 589824) {
        int j = w - 524288;
        int n = j >> 9, k = j & 511;
        o3[j] = __float2half_rn(Wt1[k * 128 + n]);
    }
}

// ---------------------------------------------------------------------------
// Tile loader halves: 128 rows x 64 fp16, row stride D halfs, kb in halfs.
// ---------------------------------------------------------------------------
template <bool CHK>
__device__ __forceinline__ void load_half_tile(
    uint32_t s, const __half* __restrict__ G, int rowBase, int kb, int E, int tid)
{
#pragma unroll
    for (int i = 0; i < 8; i++) {
        int idx = i * NTH + tid;
        int row = idx >> 3, seg = idx & 7;
        bool v = !CHK || (rowBase + row) < E;
        const __half* src = G + (size_t)(rowBase + row) * D + kb + seg * 8;
        cpa16(s + (uint32_t)(row * ROWB + seg * 16), v ? src : G, v);
    }
}

// ---------------------------------------------------------------------------
// Fragment loads (k-step = 32 bytes). Lane maps R13/R15-proven.
// ---------------------------------------------------------------------------
__device__ __forceinline__ void load_frags(
    uint32_t asB, uint32_t bsB, const uint32_t aOff[4], const uint32_t bOff[4],
    int ks, uint32_t a[4][4], uint32_t b[4][4])
{
    const uint32_t kby = (uint32_t)ks * 32;
#pragma unroll
    for (int mt = 0; mt < 4; mt++)
        ldsm4(a[mt][0], a[mt][1], a[mt][2], a[mt][3], asB + aOff[mt] + kby);
#pragma unroll
    for (int j = 0; j < 4; j++)
        ldsm4(b[j][0], b[j][1], b[j][2], b[j][3], bsB + bOff[j] + kby);
}

// ---------------------------------------------------------------------------
// Mainloop: 8 chunks of K=64, 3-stage ring, split barrier, frag dbl-buffer.
// cp.async for chunk kt+2 spread into the ks loop: A at ks0, B at ks1,
// commit at ks2 (commit exactly once per iteration — group accounting).
// Phase audit: pre arrive(1); iter kt syncs 1+(kt&1); arrive(1+((kt+1)&1))
// posted after last LDSM of chunk kt (dep-fenced), skipped at kt=7.
// ---------------------------------------------------------------------------
template <bool CHKA>
__device__ __forceinline__ void gemm_mainloop(
    char* smem, const __half* __restrict__ Ag, const __half* __restrict__ Bg,
    int rowBase, int colBase, int E, int tid, float acc[4][8][4],
    int wm, int wn, int lane)
{
    const uint32_t sb = smem_u32(smem);

    uint32_t aOff[4], bOff[4];
#pragma unroll
    for (int mt = 0; mt < 4; mt++)
        aOff[mt] = (uint32_t)((wm * 64 + mt * 16 + (lane & 15)) * ROWB
                              + (lane >> 4) * 16);
#pragma unroll
    for (int j = 0; j < 4; j++)
        bOff[j] = (uint32_t)((wn * 64 + j * 16 + (lane & 7) + ((lane & 16) ? 8 : 0)) * ROWB
                             + ((lane >> 3) & 1) * 16);

#pragma unroll
    for (int mt = 0; mt < 4; mt++)
#pragma unroll
        for (int nt = 0; nt < 8; nt++)
#pragma unroll
            for (int r = 0; r < 4; r++) acc[mt][nt][r] = 0.0f;

    load_half_tile<CHKA>(sb, Ag, rowBase, 0, E, tid);
    load_half_tile<false>(sb + TILE_BYTES, Bg, colBase, 0, E, tid);
    CP_COMMIT();
    load_half_tile<CHKA>(sb + STAGE_BYTES, Ag, rowBase, 64, E, tid);
    load_half_tile<false>(sb + STAGE_BYTES + TILE_BYTES, Bg, colBase, 64, E, tid);
    CP_COMMIT();

    BAR_ARRIVE(1);

    for (int kt = 0; kt < NCH; kt++) {
        CP_WAIT(1);
        BAR_SYNC(1 + (kt & 1));

        const uint32_t asB = sb + (uint32_t)(kt % 3) * STAGE_BYTES;
        const uint32_t bsB = asB + TILE_BYTES;
        const uint32_t st  = sb + (uint32_t)((kt + 2) % 3) * STAGE_BYTES;
        const bool more = (kt + 2 < NCH);

        uint32_t a[2][4][4], b[2][4][4];
        load_frags(asB, bsB, aOff, bOff, 0, a[0], b[0]);

#pragma unroll
        for (int ks = 0; ks < 4; ks++) {
            const int cur = ks & 1;
            if (ks < 3)
                load_frags(asB, bsB, aOff, bOff, ks + 1, a[cur ^ 1], b[cur ^ 1]);
            // Spread next-chunk loads under the MMA stream.
            if (ks == 0 && more)
                load_half_tile<CHKA>(st, Ag, rowBase, (kt + 2) * 64, E, tid);
            if (ks == 1 && more)
                load_half_tile<false>(st + TILE_BYTES, Bg, colBase, (kt + 2) * 64, E, tid);
            if (ks == 2)
                CP_COMMIT();               // exactly one group per iteration
            if (ks == 3) {
                asm volatile("" :: "r"(a[cur][0][3]), "r"(a[cur][1][3]),
                                   "r"(a[cur][2][3]), "r"(a[cur][3][3]),
                                   "r"(b[cur][0][3]), "r"(b[cur][1][3]),
                                   "r"(b[cur][2][3]), "r"(b[cur][3][3]));
                if (kt < NCH - 1) BAR_ARRIVE(1 + ((kt + 1) & 1));
            }
#pragma unroll
            for (int mt = 0; mt < 4; mt++)
#pragma unroll
                for (int nt = 0; nt < 8; nt++) {
                    const int j = nt >> 1, h = (nt & 1) * 2;
                    mma_f16(acc[mt][nt][0], acc[mt][nt][1], acc[mt][nt][2], acc[mt][nt][3],
                            a[cur][mt][0], a[cur][mt][1], a[cur][mt][2], a[cur][mt][3],
                            b[cur][j][h], b[cur][j][h + 1]);
                }
        }
    }
    CP_WAIT(0);
    __syncthreads();
}

// ---------------------------------------------------------------------------
// Big GEMM. MODE 1 (gemm1): h = fp16(relu(acc+bias)).
//          MODE 0 (gemm2): edge fp32 exact + fp16 copy for the head.
// Grid (4, rb): col block fastest -> A rows shared via L2.
// ---------------------------------------------------------------------------
template <int MODE>
__global__ __launch_bounds__(NTH) void gemm_mma(
    const __half* __restrict__ Ag, const __half* __restrict__ Bt,
    const float* __restrict__ bias, void* __restrict__ Cv,
    __half* __restrict__ Cr, int E)
{
    extern __shared__ __align__(16) char smem[];
    __shared__ float sbias[128];

    const int tid = threadIdx.x;
    const int wid = tid >> 5, lane = tid & 31;
    const int wm = wid >> 1, wn = wid & 1;
    const int gid = lane >> 2, tig = lane & 3;
    const int rowBase = blockIdx.y * 128;
    const int colBase = blockIdx.x * 128;

    sbias[tid] = bias[colBase + tid];

    float acc[4][8][4];
    gemm_mainloop<true>(smem, Ag, Bt, rowBase, colBase, E, tid, acc, wm, wn, lane);

#pragma unroll
    for (int mt = 0; mt < 4; mt++) {
        const int r0 = rowBase + wm * 64 + mt * 16 + gid;
#pragma unroll
        for (int nt = 0; nt < 8; nt++) {
            const int cl = wn * 64 + nt * 8 + tig * 2;
            const int c = colBase + cl;
            float v0 = acc[mt][nt][0] + sbias[cl];
            float v1 = acc[mt][nt][1] + sbias[cl + 1];
            float v2 = acc[mt][nt][2] + sbias[cl];
            float v3 = acc[mt][nt][3] + sbias[cl + 1];
            if (MODE == 1) {
                __half* Ch = (__half*)Cv;
                if (r0 < E)
                    *(__half2*)&Ch[(size_t)r0 * D + c] =
                        __floats2half2_rn(fmaxf(v0, 0.f), fmaxf(v1, 0.f));
                if (r0 + 8 < E)
                    *(__half2*)&Ch[(size_t)(r0 + 8) * D + c] =
                        __floats2half2_rn(fmaxf(v2, 0.f), fmaxf(v3, 0.f));
            } else {
                float* Cf = (float*)Cv;
                if (r0 < E) {
                    *(float2*)&Cf[(size_t)r0 * D + c] = make_float2(v0, v1);
                    *(__half2*)&Cr[(size_t)r0 * D + c] = __floats2half2_rn(v0, v1);
                }
                if (r0 + 8 < E) {
                    *(float2*)&Cf[(size_t)(r0 + 8) * D + c] = make_float2(v2, v3);
                    *(__half2*)&Cr[(size_t)(r0 + 8) * D + c] = __floats2half2_rn(v2, v3);
                }
            }
        }
    }
}

// ---------------------------------------------------------------------------
// Head: T1 = relu(edge_h @ Wt1 + bt1) (128x128, K=512), then per-row 128->4
// GEMV + softmax + stack + gate + small outputs.
// ---------------------------------------------------------------------------
__global__ __launch_bounds__(NTH) void head_mma(
    const __half* __restrict__ EEh, const __half* __restrict__ Wt1t,
    const float* __restrict__ bt1, const float* __restrict__ Wt2,
    const float* __restrict__ bt2, float* __restrict__ out, int E)
{
    extern __shared__ __align__(16) char smem[];
    __shared__ float sWt2[512];
    __shared__ float sbt1[128];

    const int tid = threadIdx.x;
    const int wid = tid >> 5, lane = tid & 31;
    const int wm = wid >> 1, wn = wid & 1;
    const int gid = lane >> 2, tig = lane & 3;
    const int rowBase = blockIdx.x * 128;

    sbt1[tid] = bt1[tid];
    sWt2[tid]       = Wt2[tid];
    sWt2[tid + 128] = Wt2[tid + 128];
    sWt2[tid + 256] = Wt2[tid + 256];
    sWt2[tid + 384] = Wt2[tid + 384];

    float acc[4][8][4];
    gemm_mainloop<true>(smem, EEh, Wt1t, rowBase, 0, E, tid, acc, wm, wn, lane);

    float* T1 = (float*)smem;
#pragma unroll
    for (int mt = 0; mt < 4; mt++) {
        const int r = wm * 64 + mt * 16 + gid;
#pragma unroll
        for (int nt = 0; nt < 8; nt++) {
            const int c = wn * 64 + nt * 8 + tig * 2;
            T1[r * 129 + c]           = fmaxf(acc[mt][nt][0] + sbt1[c], 0.f);
            T1[r * 129 + c + 1]       = fmaxf(acc[mt][nt][1] + sbt1[c + 1], 0.f);
            T1[(r + 8) * 129 + c]     = fmaxf(acc[mt][nt][2] + sbt1[c], 0.f);
            T1[(r + 8) * 129 + c + 1] = fmaxf(acc[mt][nt][3] + sbt1[c + 1], 0.f);
        }
    }
    __syncthreads();

    {
        const int gr = rowBase + tid;
        if (gr < E) {
            float t0 = __ldg(&bt2[0]), t1 = __ldg(&bt2[1]);
            float t2 = __ldg(&bt2[2]), t3 = __ldg(&bt2[3]);
            const float* rp = T1 + tid * 129;
#pragma unroll 8
            for (int k = 0; k < 128; k++) {
                float x = rp[k];
                t0 = fmaf(x, sWt2[k * 4 + 0], t0);
                t1 = fmaf(x, sWt2[k * 4 + 1], t1);
                t2 = fmaf(x, sWt2[k * 4 + 2], t2);
                t3 = fmaf(x, sWt2[k * 4 + 3], t3);
            }
            float m = fmaxf(fmaxf(t0, t1), fmaxf(t2, t3));
            float e0 = __expf(t0 - m), e1 = __expf(t1 - m);
            float e2 = __expf(t2 - m), e3 = __expf(t3 - m);
            float inv = 1.0f / (e0 + e1 + e2 + e3);
            float p0 = e0 * inv, p1 = e1 * inv, p2 = e2 * inv, p3 = e3 * inv;
            float tw0 = 1.0f - p0;

            const size_t Es = (size_t)E;
            out[0 * Es + gr] = tw0;
            out[1 * Es + gr] = p1;
            out[2 * Es + gr] = p2;
            out[3 * Es + gr] = p3;
            float* mw = out + 4 * Es;
            mw[0 * Es + gr] = gatef(tw0);
            mw[1 * Es + gr] = gatef(p1);
            mw[2 * Es + gr] = gatef(p2);
            mw[3 * Es + gr] = gatef(p3);
            float* to = out + 8 * Es;
            to[(size_t)gr * 4 + 0] = p0;
            to[(size_t)gr * 4 + 1] = p1;
            to[(size_t)gr * 4 + 2] = p2;
            to[(size_t)gr * 4 + 3] = p3;
        }
    }
}

// ---------------------------------------------------------------------------
extern "C" void kernel_launch(void* const* d_in, const int* in_sizes, int n_in,
                              void* d_out, int out_size)
{
    const float* pred = (const float*)d_in[1];
    const float* We1  = (const float*)d_in[2];
    const float* be1  = (const float*)d_in[3];
    const float* We2  = (const float*)d_in[4];
    const float* be2  = (const float*)d_in[5];
    const float* Wt1  = (const float*)d_in[6];
    const float* bt1  = (const float*)d_in[7];
    const float* Wt2  = (const float*)d_in[8];
    const float* bt2  = (const float*)d_in[9];

    const int E = in_sizes[1] / D;
    float* out  = (float*)d_out;
    float* edge = out + (size_t)12 * E;

    __half *pHH, *pPH, *pW1t, *pW2t, *pWt1t;
    cudaGetSymbolAddress((void**)&pHH,   g_hh);
    cudaGetSymbolAddress((void**)&pPH,   g_ph);
    cudaGetSymbolAddress((void**)&pW1t,  g_W1t);
    cudaGetSymbolAddress((void**)&pW2t,  g_W2t);
    cudaGetSymbolAddress((void**)&pWt1t, g_Wt1t);

    cudaFuncSetAttribute(gemm_mma<1>,
                         cudaFuncAttributeMaxDynamicSharedMemorySize, SMEM_TOTAL);
    cudaFuncSetAttribute(gemm_mma<0>,
                         cudaFuncAttributeMaxDynamicSharedMemorySize, SMEM_TOTAL);
    cudaFuncSetAttribute(head_mma,
                         cudaFuncAttributeMaxDynamicSharedMemorySize, SMEM_TOTAL);

    const int n4 = E * D / 4;
    const int prep_total = n4 + 589824;
    prep_all<<<(prep_total + 255) / 256, 256>>>(
        (const float4*)pred, (__half2*)pPH, We1, We2, Wt1,
        pW1t, pW2t, pWt1t, n4);

    const int rb = (E + 127) / 128;
    dim3 grid(4, rb);   // col block fastest -> A rows shared via L2

    gemm_mma<1><<<grid, NTH, SMEM_TOTAL>>>(pPH, pW1t, be1, (void*)pHH, nullptr, E);
    gemm_mma<0><<<grid, NTH, SMEM_TOTAL>>>(pHH, pW2t, be2, (void*)edge, pPH, E);
    head_mma<<<rb, NTH, SMEM_TOTAL>>>(pPH, pWt1t, bt1, Wt2, bt2, out, E);
}